// round 6
// baseline (speedup 1.0000x reference)
#include <cuda_runtime.h>

#define BB 8192
#define DD 64
#define KK 32
#define HID 16

#define KG 2        // k per block
#define BT 128      // b per block (4 per lane)
#define NT 256      // 8 warps: warp w -> kw = w&1, dq = w>>1 (d-quarter)
#define XPITCH 132  // padded row stride for transposed x in smem (floats)

// smem layout (floats)
#define SW_SZ   (KG * DD * 32)   // 4096 : per (k,d): [0:16)=A2, [16:32)=t
#define SL_SZ   (KG * DD)        // 128  : linear coeff per (k,d)
#define SC_SZ   (KG * DD)        // 128  : constant per (k,d)
#define SXT_SZ  (DD * XPITCH)    // 8448 : x tile; later reused: partials + out tile
#define SOP_SZ  (KG * 32)        // 64   : outer A2/t
#define SMEM_FLOATS (SW_SZ + SL_SZ + SC_SZ + SXT_SZ + KG + SOP_SZ + KG + KG)

// ---------------------------------------------------------
// Fused kernel. Identity: w2*relu(w1*x+b1) == A2*max(x,t) + L*x + C with
//   w1>0: A2= w1*w2, t=-b1/w1, C+=w2*b1
//   w1<0: A2=-w1*w2, t=-b1/w1, L+=w1*w2
//   w1=0: C += w2*relu(b1)
// ---------------------------------------------------------
__global__ void __launch_bounds__(NT, 4)
kan_fused(const float* __restrict__ x,
          const float* __restrict__ iw1, const float* __restrict__ ib1,
          const float* __restrict__ iw2, const float* __restrict__ ib2,
          const float* __restrict__ ow1, const float* __restrict__ ob1,
          const float* __restrict__ ow2, const float* __restrict__ ob2,
          float* __restrict__ out) {
    extern __shared__ float sm[];
    float* sw  = sm;                 // SW_SZ
    float* sL  = sw  + SW_SZ;        // SL_SZ
    float* sC  = sL  + SL_SZ;        // SC_SZ
    float* sxT = sC  + SC_SZ;        // SXT_SZ
    float* sCk = sxT + SXT_SZ;       // KG
    float* sop = sCk + KG;           // SOP_SZ
    float* soL = sop + SOP_SZ;       // KG
    float* soC = soL + KG;           // KG

    const int t  = threadIdx.x;
    const int w  = t >> 5;
    const int l  = t & 31;
    const int kw = w & 1;            // which k this warp serves
    const int dq = w >> 1;           // which d-quarter (16 d each)
    const int k0 = blockIdx.y * KG;
    const int b0 = blockIdx.x * BT;

    // ---------------- Phase A: per-block prep (threads 0..127: 1 (k,d) each) ----------------
    if (t < KG * DD) {
        int kd = t;                              // 0..127; k = kd>>6, d = kd&63
        long g = ((long)(k0 + (kd >> 6)) * DD + (kd & 63)) * HID;
        const float4* W1 = (const float4*)(iw1 + g);
        const float4* B1 = (const float4*)(ib1 + g);
        const float4* W2 = (const float4*)(iw2 + g);
        float L = 0.f, C = ib2[k0 * DD + kd];
        float4* swa = (float4*)(sw + kd * 32);
        float4* swt = swa + 4;
#pragma unroll
        for (int q = 0; q < 4; q++) {
            float4 av = W1[q], bv = B1[q], cv = W2[q];
            float4 A2v, tv;
            {
                float a = av.x, b = bv.x, c = cv.x, ac = a * c;
                if (a > 0.f)      { A2v.x = ac;  tv.x = __fdividef(-b, a); C += c * b; }
                else if (a < 0.f) { A2v.x = -ac; tv.x = __fdividef(-b, a); L += ac; }
                else              { A2v.x = 0.f; tv.x = 0.f; C += c * fmaxf(b, 0.f); }
            }
            {
                float a = av.y, b = bv.y, c = cv.y, ac = a * c;
                if (a > 0.f)      { A2v.y = ac;  tv.y = __fdividef(-b, a); C += c * b; }
                else if (a < 0.f) { A2v.y = -ac; tv.y = __fdividef(-b, a); L += ac; }
                else              { A2v.y = 0.f; tv.y = 0.f; C += c * fmaxf(b, 0.f); }
            }
            {
                float a = av.z, b = bv.z, c = cv.z, ac = a * c;
                if (a > 0.f)      { A2v.z = ac;  tv.z = __fdividef(-b, a); C += c * b; }
                else if (a < 0.f) { A2v.z = -ac; tv.z = __fdividef(-b, a); L += ac; }
                else              { A2v.z = 0.f; tv.z = 0.f; C += c * fmaxf(b, 0.f); }
            }
            {
                float a = av.w, b = bv.w, c = cv.w, ac = a * c;
                if (a > 0.f)      { A2v.w = ac;  tv.w = __fdividef(-b, a); C += c * b; }
                else if (a < 0.f) { A2v.w = -ac; tv.w = __fdividef(-b, a); L += ac; }
                else              { A2v.w = 0.f; tv.w = 0.f; C += c * fmaxf(b, 0.f); }
            }
            swa[q] = A2v;
            swt[q] = tv;
        }
        sL[kd] = L;
        sC[kd] = C;
    }

    // Outer-net prep: one thread per k.
    if (t < KG) {
        int k = k0 + t;
        float L = 0.f, C = ob2[k];
        float* op = sop + t * 32;
#pragma unroll
        for (int h = 0; h < HID; h++) {
            float a = ow1[k * HID + h], b = ob1[k * HID + h], c = ow2[k * HID + h];
            float ac = a * c, A2, tt;
            if (a > 0.f)      { A2 = ac;  tt = __fdividef(-b, a); C += c * b; }
            else if (a < 0.f) { A2 = -ac; tt = __fdividef(-b, a); L += ac; }
            else              { A2 = 0.f; tt = 0.f; C += c * fmaxf(b, 0.f); }
            op[h] = A2; op[16 + h] = tt;
        }
        soL[t] = L; soC[t] = C;
    }

    // Stage x transposed: sxT[d][b]
    {
        const float4* gx = (const float4*)(x + (long)b0 * DD);
#pragma unroll
        for (int it = 0; it < (BT * DD / 4) / NT; it++) {
            int c   = t + it * NT;
            int row = c >> 4;       // b within tile
            int dc  = c & 15;       // float4 index within row
            float4 v = gx[c];
            int d = dc * 4;
            sxT[(d + 0) * XPITCH + row] = v.x;
            sxT[(d + 1) * XPITCH + row] = v.y;
            sxT[(d + 2) * XPITCH + row] = v.z;
            sxT[(d + 3) * XPITCH + row] = v.w;
        }
    }
    __syncthreads();

    // Per-k constant = sum_d C (warps 0..1 reduce their k's 64 values)
    if (w < KG) {
        float v = sC[w * 64 + l] + sC[w * 64 + 32 + l];
#pragma unroll
        for (int o = 16; o > 0; o >>= 1) v += __shfl_xor_sync(0xffffffffu, v, o);
        if (l == 0) sCk[w] = v;
    }
    __syncthreads();

    // ---------------- Phase B: main evaluation (each warp: 16 d) ----------------
    // Per sample per d: 16 FMNMX (alu) + 17 FFMA (fma); two accumulator chains
    // per sample (h0-7 / h8-15).
    float aA[4] = {0.f, 0.f, 0.f, 0.f};
    float aB[4] = {0.f, 0.f, 0.f, 0.f};
    float aL[4] = {0.f, 0.f, 0.f, 0.f};

    const float* wbase = sw + kw * DD * 32;
    const float* lbase = sL + kw * DD;
    const int d0 = dq * 16;

#pragma unroll 4
    for (int dd = 0; dd < 16; dd++) {
        const int d = d0 + dd;
        const float4* wp = (const float4*)(wbase + d * 32);
        float  Ld = lbase[d];
        float4 xv = *(const float4*)(sxT + d * XPITCH + (l << 2));
        float xs[4] = {xv.x, xv.y, xv.z, xv.w};

        // first half: h0..7 -> aA
        {
            float4 a0 = wp[0], a1 = wp[1];
            float4 t0 = wp[4], t1 = wp[5];
#pragma unroll
            for (int s = 0; s < 4; s++) {
                float xx = xs[s];
                aL[s] = fmaf(Ld, xx, aL[s]);
                float acc = aA[s];
                acc = fmaf(a0.x, fmaxf(xx, t0.x), acc);
                acc = fmaf(a0.y, fmaxf(xx, t0.y), acc);
                acc = fmaf(a0.z, fmaxf(xx, t0.z), acc);
                acc = fmaf(a0.w, fmaxf(xx, t0.w), acc);
                acc = fmaf(a1.x, fmaxf(xx, t1.x), acc);
                acc = fmaf(a1.y, fmaxf(xx, t1.y), acc);
                acc = fmaf(a1.z, fmaxf(xx, t1.z), acc);
                acc = fmaf(a1.w, fmaxf(xx, t1.w), acc);
                aA[s] = acc;
            }
        }
        // second half: h8..15 -> aB
        {
            float4 a2 = wp[2], a3 = wp[3];
            float4 t2 = wp[6], t3 = wp[7];
#pragma unroll
            for (int s = 0; s < 4; s++) {
                float xx = xs[s];
                float acc = aB[s];
                acc = fmaf(a2.x, fmaxf(xx, t2.x), acc);
                acc = fmaf(a2.y, fmaxf(xx, t2.y), acc);
                acc = fmaf(a2.z, fmaxf(xx, t2.z), acc);
                acc = fmaf(a2.w, fmaxf(xx, t2.w), acc);
                acc = fmaf(a3.x, fmaxf(xx, t3.x), acc);
                acc = fmaf(a3.y, fmaxf(xx, t3.y), acc);
                acc = fmaf(a3.z, fmaxf(xx, t3.z), acc);
                acc = fmaf(a3.w, fmaxf(xx, t3.w), acc);
                aB[s] = acc;
            }
        }
    }

    // ---------------- Phase C: combine d-quarters, outer net, store ----------------
    float* sPart = sxT;              // 1024 floats: [dq][kw][b_local]
    __syncthreads();                 // main loop done reading sxT
    {
        float s0 = aA[0] + aB[0] + aL[0];
        float s1 = aA[1] + aB[1] + aL[1];
        float s2 = aA[2] + aB[2] + aL[2];
        float s3 = aA[3] + aB[3] + aL[3];
        *(float4*)(sPart + dq * (KG * BT) + kw * BT + (l << 2)) = make_float4(s0, s1, s2, s3);
    }
    __syncthreads();

    float* sOut = sxT + 1024;        // BT*KG floats: sOut[b][kw]
    if (dq == 0) {
        float4 p0 = *(const float4*)(sPart + 0 * (KG * BT) + kw * BT + (l << 2));
        float4 p1 = *(const float4*)(sPart + 1 * (KG * BT) + kw * BT + (l << 2));
        float4 p2 = *(const float4*)(sPart + 2 * (KG * BT) + kw * BT + (l << 2));
        float4 p3 = *(const float4*)(sPart + 3 * (KG * BT) + kw * BT + (l << 2));
        const float Ck  = sCk[kw];
        const float oLk = soL[kw];
        const float oCk = soC[kw];
        float oA[16], oT[16];
#pragma unroll
        for (int h = 0; h < 16; h++) { oA[h] = sop[kw * 32 + h]; oT[h] = sop[kw * 32 + 16 + h]; }

        float sk[4] = {p0.x + p1.x + p2.x + p3.x,
                       p0.y + p1.y + p2.y + p3.y,
                       p0.z + p1.z + p2.z + p3.z,
                       p0.w + p1.w + p2.w + p3.w};
#pragma unroll
        for (int j = 0; j < 4; j++) {
            float s = sk[j] + Ck;
            float r = fmaf(oLk, s, oCk);
#pragma unroll
            for (int h = 0; h < 16; h++)
                r = fmaf(oA[h], fmaxf(s, oT[h]), r);
            sOut[((l << 2) + j) * KG + kw] = r;
        }
    }
    __syncthreads();

    if (t < BT) {
        float2 v = make_float2(sOut[t * KG + 0], sOut[t * KG + 1]);
        *(float2*)(out + (long)(b0 + t) * KK + k0) = v;
    }
}

// ---------------------------------------------------------
extern "C" void kernel_launch(void* const* d_in, const int* in_sizes, int n_in,
                              void* d_out, int out_size) {
    const float* x   = (const float*)d_in[0];
    const float* iw1 = (const float*)d_in[1];
    const float* ib1 = (const float*)d_in[2];
    const float* iw2 = (const float*)d_in[3];
    const float* ib2 = (const float*)d_in[4];
    const float* ow1 = (const float*)d_in[5];
    const float* ob1 = (const float*)d_in[6];
    const float* ow2 = (const float*)d_in[7];
    const float* ob2 = (const float*)d_in[8];
    float* out = (float*)d_out;

    const int smem = SMEM_FLOATS * 4;
    cudaFuncSetAttribute(kan_fused, cudaFuncAttributeMaxDynamicSharedMemorySize, smem);

    dim3 grid(BB / BT, KK / KG);
    kan_fused<<<grid, NT, smem>>>(x, iw1, ib1, iw2, ib2, ow1, ob1, ow2, ob2, out);
}

// round 8
// speedup vs baseline: 1.2074x; 1.2074x over previous
#include <cuda_runtime.h>

#define BB 8192
#define DD 64
#define KK 32
#define HID 16

#define KG 8        // k per block (one k per warp)
#define BT 128      // b per block (4 per lane)
#define NT 256      // threads per block
#define XPITCH 132  // padded row stride for transposed x in smem (floats)

// smem layout (floats)
#define SW_SZ   (KG * DD * 32)   // 16384 : per (k,d): [0:16)=A2, [16:32)=t
#define SL_SZ   (KG * DD)        // 512   : linear coeff per (k,d)
#define SC_SZ   (KG * DD)        // 512   : constant per (k,d)
#define SXT_SZ  (DD * XPITCH)    // 8448  : x tile; reused as out tile
#define SOP_SZ  (KG * 32)        // 256   : outer A2/t
#define SMEM_FLOATS (SW_SZ + SL_SZ + SC_SZ + SXT_SZ + KG + SOP_SZ + KG + KG)

// -------- device scratch (transformed weights; written once by kan_prep) ---
__device__ float g_wpack[KK * DD * 32];  // per (k,d): [0:16)=A2, [16:32)=t
__device__ float g_tL[KK * DD];
__device__ float g_tC[KK * DD];          // per-(k,d) constant (incl ib2)
__device__ float g_oPack[KK * 32];       // outer: [0:16)=A2, [16:32)=t
__device__ float g_oL[KK];
__device__ float g_oC[KK];

// ---------------------------------------------------------
// Prep: one thread per (k,d, h-quad). 8192 threads total, 4 MUFU each.
// Identity: w2*relu(w1*x+b1) == A2*max(x,t) + L*x + C with
//   w1>0: A2= w1*w2, t=-b1/w1, C+=w2*b1
//   w1<0: A2=-w1*w2, t=-b1/w1, L+=w1*w2
//   w1=0: C += w2*relu(b1)
// ---------------------------------------------------------
__global__ void kan_prep(const float* __restrict__ iw1, const float* __restrict__ ib1,
                         const float* __restrict__ iw2, const float* __restrict__ ib2,
                         const float* __restrict__ ow1, const float* __restrict__ ob1,
                         const float* __restrict__ ow2, const float* __restrict__ ob2) {
    int tid = blockIdx.x * blockDim.x + threadIdx.x;   // 0 .. KK*DD*4-1
    int kd  = tid >> 2;
    int q   = tid & 3;

    long g = (long)kd * HID + q * 4;
    float4 av = *(const float4*)(iw1 + g);
    float4 bv = *(const float4*)(ib1 + g);
    float4 cv = *(const float4*)(iw2 + g);

    float L = 0.f, C = 0.f;
    float4 A2v, tv;
    {
        float a = av.x, b = bv.x, c = cv.x, ac = a * c;
        if (a > 0.f)      { A2v.x = ac;  tv.x = __fdividef(-b, a); C += c * b; }
        else if (a < 0.f) { A2v.x = -ac; tv.x = __fdividef(-b, a); L += ac; }
        else              { A2v.x = 0.f; tv.x = 0.f; C += c * fmaxf(b, 0.f); }
    }
    {
        float a = av.y, b = bv.y, c = cv.y, ac = a * c;
        if (a > 0.f)      { A2v.y = ac;  tv.y = __fdividef(-b, a); C += c * b; }
        else if (a < 0.f) { A2v.y = -ac; tv.y = __fdividef(-b, a); L += ac; }
        else              { A2v.y = 0.f; tv.y = 0.f; C += c * fmaxf(b, 0.f); }
    }
    {
        float a = av.z, b = bv.z, c = cv.z, ac = a * c;
        if (a > 0.f)      { A2v.z = ac;  tv.z = __fdividef(-b, a); C += c * b; }
        else if (a < 0.f) { A2v.z = -ac; tv.z = __fdividef(-b, a); L += ac; }
        else              { A2v.z = 0.f; tv.z = 0.f; C += c * fmaxf(b, 0.f); }
    }
    {
        float a = av.w, b = bv.w, c = cv.w, ac = a * c;
        if (a > 0.f)      { A2v.w = ac;  tv.w = __fdividef(-b, a); C += c * b; }
        else if (a < 0.f) { A2v.w = -ac; tv.w = __fdividef(-b, a); L += ac; }
        else              { A2v.w = 0.f; tv.w = 0.f; C += c * fmaxf(b, 0.f); }
    }
    *(float4*)(g_wpack + kd * 32 + q * 4)      = A2v;
    *(float4*)(g_wpack + kd * 32 + 16 + q * 4) = tv;

    // quad-reduce L and C (lanes 4j..4j+3 share kd)
    L += __shfl_down_sync(0xffffffffu, L, 1, 4);
    L += __shfl_down_sync(0xffffffffu, L, 2, 4);
    C += __shfl_down_sync(0xffffffffu, C, 1, 4);
    C += __shfl_down_sync(0xffffffffu, C, 2, 4);
    if (q == 0) {
        g_tL[kd] = L;
        g_tC[kd] = C + ib2[kd];
    }

    // Outer nets: threads 0..31 (k = tid), serial over HID.
    if (tid < KK) {
        int k = tid;
        float Lo = 0.f, Co = ob2[k];
#pragma unroll
        for (int h = 0; h < HID; h++) {
            float a = ow1[k * HID + h], b = ob1[k * HID + h], c = ow2[k * HID + h];
            float ac = a * c, A2, tt;
            if (a > 0.f)      { A2 = ac;  tt = __fdividef(-b, a); Co += c * b; }
            else if (a < 0.f) { A2 = -ac; tt = __fdividef(-b, a); Lo += ac; }
            else              { A2 = 0.f; tt = 0.f; Co += c * fmaxf(b, 0.f); }
            g_oPack[k * 32 + h]      = A2;
            g_oPack[k * 32 + 16 + h] = tt;
        }
        g_oL[k] = Lo;
        g_oC[k] = Co;
    }
}

// ---------------------------------------------------------
// Main kernel: warp = fixed k, lanes carry 4 b's each.
// Per sample per d: 16 FMNMX (alu) + 17 FFMA (fma). No MUFU anywhere.
// ---------------------------------------------------------
__device__ __forceinline__ float kan_step(float xx, float acc, float Ld,
                                          const float4 wa[4], const float4 wt[4]) {
    acc = fmaf(Ld, xx, acc);
#pragma unroll
    for (int q = 0; q < 4; q++) {
        acc = fmaf(wa[q].x, fmaxf(xx, wt[q].x), acc);
        acc = fmaf(wa[q].y, fmaxf(xx, wt[q].y), acc);
        acc = fmaf(wa[q].z, fmaxf(xx, wt[q].z), acc);
        acc = fmaf(wa[q].w, fmaxf(xx, wt[q].w), acc);
    }
    return acc;
}

__global__ void __launch_bounds__(NT, 2)
kan_main(const float* __restrict__ x, float* __restrict__ out) {
    extern __shared__ float sm[];
    float* sw  = sm;                 // SW_SZ
    float* sL  = sw  + SW_SZ;        // SL_SZ
    float* sC  = sL  + SL_SZ;        // SC_SZ
    float* sxT = sC  + SC_SZ;        // SXT_SZ
    float* sCk = sxT + SXT_SZ;       // KG
    float* sop = sCk + KG;           // SOP_SZ
    float* soL = sop + SOP_SZ;       // KG
    float* soC = soL + KG;           // KG

    const int t  = threadIdx.x;
    const int w  = t >> 5;
    const int l  = t & 31;
    const int k0 = blockIdx.y * KG;
    const int b0 = blockIdx.x * BT;

    // Stage transformed weights (coalesced, 16 float4/thread)
    {
        const float4* gw  = (const float4*)(g_wpack + k0 * DD * 32);
        float4*       swv = (float4*)sw;
#pragma unroll
        for (int i = 0; i < (SW_SZ / 4) / NT; i++)
            swv[t + i * NT] = gw[t + i * NT];
    }
#pragma unroll
    for (int i = 0; i < SL_SZ / NT; i++) sL[t + i * NT] = g_tL[k0 * DD + t + i * NT];
#pragma unroll
    for (int i = 0; i < SC_SZ / NT; i++) sC[t + i * NT] = g_tC[k0 * DD + t + i * NT];
    for (int i = t; i < SOP_SZ; i += NT) sop[i] = g_oPack[k0 * 32 + i];
    if (t < KG) { soL[t] = g_oL[k0 + t]; soC[t] = g_oC[k0 + t]; }

    // Stage x transposed: sxT[d][b]
    {
        const float4* gx = (const float4*)(x + (long)b0 * DD);
#pragma unroll
        for (int it = 0; it < (BT * DD / 4) / NT; it++) {
            int c   = t + it * NT;
            int row = c >> 4;       // b within tile
            int dc  = c & 15;       // float4 index within row
            float4 v = gx[c];
            int d = dc * 4;
            sxT[(d + 0) * XPITCH + row] = v.x;
            sxT[(d + 1) * XPITCH + row] = v.y;
            sxT[(d + 2) * XPITCH + row] = v.z;
            sxT[(d + 3) * XPITCH + row] = v.w;
        }
    }
    __syncthreads();

    // Per-k constant = sum_d C (warp w reduces its 64 values)
    {
        float v = sC[w * 64 + l] + sC[w * 64 + 32 + l];
#pragma unroll
        for (int o = 16; o > 0; o >>= 1) v += __shfl_xor_sync(0xffffffffu, v, o);
        if (l == 0) sCk[w] = v;
    }
    __syncthreads();

    // ---------------- main evaluation ----------------
    float acc0 = 0.f, acc1 = 0.f, acc2 = 0.f, acc3 = 0.f;
    const float* wbase = sw + w * DD * 32;
    const float* lbase = sL + w * DD;

#pragma unroll 2
    for (int d = 0; d < DD; d++) {
        const float4* wp = (const float4*)(wbase + d * 32);
        float4 wa[4], wt[4];
#pragma unroll
        for (int q = 0; q < 4; q++) wa[q] = wp[q];
#pragma unroll
        for (int q = 0; q < 4; q++) wt[q] = wp[4 + q];
        float  Ld = lbase[d];
        float4 xv = *(const float4*)(sxT + d * XPITCH + (l << 2));
        acc0 = kan_step(xv.x, acc0, Ld, wa, wt);
        acc1 = kan_step(xv.y, acc1, Ld, wa, wt);
        acc2 = kan_step(xv.z, acc2, Ld, wa, wt);
        acc3 = kan_step(xv.w, acc3, Ld, wa, wt);
    }

    // Outer net
    const float Ck  = sCk[w];
    const float oLk = soL[w];
    const float oCk = soC[w];
    float oA[16], oT[16];
#pragma unroll
    for (int h = 0; h < 16; h++) { oA[h] = sop[w * 32 + h]; oT[h] = sop[w * 32 + 16 + h]; }

    float res[4];
    float accs[4] = {acc0, acc1, acc2, acc3};
#pragma unroll
    for (int j = 0; j < 4; j++) {
        float s = accs[j] + Ck;
        float r = fmaf(oLk, s, oCk);
#pragma unroll
        for (int h = 0; h < 16; h++)
            r = fmaf(oA[h], fmaxf(s, oT[h]), r);
        res[j] = r;
    }

    // Coalesced store via smem transpose (pitch 9)
    float* sOut = sxT;
    __syncthreads();
#pragma unroll
    for (int j = 0; j < 4; j++)
        sOut[(4 * l + j) * 9 + w] = res[j];
    __syncthreads();

    if (t < BT) {
        float v0 = sOut[t * 9 + 0], v1 = sOut[t * 9 + 1];
        float v2 = sOut[t * 9 + 2], v3 = sOut[t * 9 + 3];
        float v4 = sOut[t * 9 + 4], v5 = sOut[t * 9 + 5];
        float v6 = sOut[t * 9 + 6], v7 = sOut[t * 9 + 7];
        float4* o = (float4*)(out + (long)(b0 + t) * KK + k0);
        o[0] = make_float4(v0, v1, v2, v3);
        o[1] = make_float4(v4, v5, v6, v7);
    }
}

// ---------------------------------------------------------
extern "C" void kernel_launch(void* const* d_in, const int* in_sizes, int n_in,
                              void* d_out, int out_size) {
    const float* x   = (const float*)d_in[0];
    const float* iw1 = (const float*)d_in[1];
    const float* ib1 = (const float*)d_in[2];
    const float* iw2 = (const float*)d_in[3];
    const float* ib2 = (const float*)d_in[4];
    const float* ow1 = (const float*)d_in[5];
    const float* ob1 = (const float*)d_in[6];
    const float* ow2 = (const float*)d_in[7];
    const float* ob2 = (const float*)d_in[8];
    float* out = (float*)d_out;

    const int smem = SMEM_FLOATS * 4;
    cudaFuncSetAttribute(kan_main, cudaFuncAttributeMaxDynamicSharedMemorySize, smem);

    kan_prep<<<(KK * DD * 4) / 256, 256>>>(iw1, ib1, iw2, ib2, ow1, ob1, ow2, ob2);

    dim3 grid(BB / BT, KK / KG);
    kan_main<<<grid, NT, smem>>>(x, out);
}